// round 12
// baseline (speedup 1.0000x reference)
#include <cuda_runtime.h>
#include <cuda_bf16.h>
#include <math.h>
#include <stdint.h>

// Problem constants
#define B_   2
#define T_   2048
#define C_   1024
#define H_   16
#define KD_  64
#define VD_  128
#define VBD_ 2048
#define M_   (B_ * T_)   // 4096 rows

// ---------------------------------------------------------------------------
// Scratch (static device globals -- no allocation allowed)
// ---------------------------------------------------------------------------
__device__ float g_v [(size_t)M_ * 2048];   // [B*T, VBD] (fp32)
__device__ float g_g [(size_t)M_ * 2048];   // [B*T, VBD] gate (fp32)

// bf16 [hi|lo] buffers
__device__ uint16_t g_x2  [(size_t)M_   * 2048];  // x     [4096, 2*1024]
__device__ uint16_t g_wqk2[(size_t)2048 * 2048];  // W_qk^T[2048, 2*1024]
__device__ uint16_t g_wv2 [(size_t)2048 * 2048];  // W_v^T
__device__ uint16_t g_wg2 [(size_t)2048 * 2048];  // W_g^T
__device__ uint16_t g_wo2 [(size_t)1024 * 4096];  // W_o^T [1024, 2*2048]
__device__ uint16_t g_y2  [(size_t)M_   * 4096];  // y     [4096, 2*2048] (attn writes)

// attention operands (head-major, [hi|lo])
__device__ uint16_t g_q2 [(size_t)B_ * H_ * T_ * 128];   // [bh, t, 2*64]
__device__ uint16_t g_k2 [(size_t)B_ * H_ * T_ * 128];   // [bh, t, 2*64]
__device__ uint16_t g_vt2[(size_t)B_ * H_ * VD_ * 4096]; // [bh, v, 2*2048] over s

// ---------------------------------------------------------------------------
// bf16 split helpers
// ---------------------------------------------------------------------------
__device__ __forceinline__ uint16_t f2bf(float x) {
    __nv_bfloat16 h = __float2bfloat16_rn(x);
    return *reinterpret_cast<uint16_t*>(&h);
}
__device__ __forceinline__ float bf2f(uint16_t u) {
    __nv_bfloat16 h = *reinterpret_cast<__nv_bfloat16*>(&u);
    return __bfloat162float(h);
}

// ---------------------------------------------------------------------------
// split_rows: fp32 [R,K] -> bf16 [R,2K] = [hi | lo]
// ---------------------------------------------------------------------------
__global__ void __launch_bounds__(256)
split_rows(const float* __restrict__ in, uint16_t* __restrict__ out, int R, int K)
{
    const int q4 = K >> 2;
    int i = blockIdx.x * blockDim.x + threadIdx.x;
    if (i >= R * q4) return;
    const int m = i / q4, q = i % q4;
    float4 v = *(const float4*)(in + (size_t)m * K + q * 4);
    ushort4 hi, lo;
    hi.x = f2bf(v.x); lo.x = f2bf(v.x - bf2f(hi.x));
    hi.y = f2bf(v.y); lo.y = f2bf(v.y - bf2f(hi.y));
    hi.z = f2bf(v.z); lo.z = f2bf(v.z - bf2f(hi.z));
    hi.w = f2bf(v.w); lo.w = f2bf(v.w - bf2f(hi.w));
    uint16_t* o = out + (size_t)m * 2 * K + q * 4;
    *(ushort4*)(o)     = hi;
    *(ushort4*)(o + K) = lo;
}

// ---------------------------------------------------------------------------
// split_transpose_all: all 4 weights in one launch (grid.z selects)
// ---------------------------------------------------------------------------
__global__ void __launch_bounds__(256)
split_transpose_all(const float* __restrict__ Wqk, const float* __restrict__ Wv,
                    const float* __restrict__ Wg,  const float* __restrict__ Wo)
{
    const int z = blockIdx.z;
    const float* W;
    uint16_t* out;
    int K, N;
    if (z == 0)      { W = Wqk; out = g_wqk2; K = 1024; N = 2048; }
    else if (z == 1) { W = Wv;  out = g_wv2;  K = 1024; N = 2048; }
    else if (z == 2) { W = Wg;  out = g_wg2;  K = 1024; N = 2048; }
    else             { W = Wo;  out = g_wo2;  K = 2048; N = 1024; }

    const int n0 = blockIdx.x * 32, k0 = blockIdx.y * 32;
    if (n0 >= N || k0 >= K) return;

    __shared__ float t[32][33];
    const int tx = threadIdx.x, ty = threadIdx.y;
#pragma unroll
    for (int j = 0; j < 4; j++)
        t[ty + j * 8][tx] = W[(size_t)(k0 + ty + j * 8) * N + n0 + tx];
    __syncthreads();
#pragma unroll
    for (int j = 0; j < 4; j++) {
        const int n = n0 + ty + j * 8;
        const float v = t[tx][ty + j * 8];
        const uint16_t hi = f2bf(v);
        const uint16_t lo = f2bf(v - bf2f(hi));
        uint16_t* o = out + (size_t)n * 2 * K + k0 + tx;
        o[0] = hi;
        o[K] = lo;
    }
}

// ---------------------------------------------------------------------------
// transpose_split_v: g_v [B*T, 2048] -> g_vt2 [bh, v, 2*2048] ([hi|lo] over s)
// ---------------------------------------------------------------------------
__global__ void __launch_bounds__(256)
transpose_split_v()
{
    __shared__ float t[32][33];
    const int tx = threadIdx.x, ty = threadIdx.y;
    const int s0 = blockIdx.x * 32;
    const int v0 = blockIdx.y * 32;
    const int bh = blockIdx.z;
    const int b  = bh >> 4;
    const int h  = bh & 15;
#pragma unroll
    for (int j = 0; j < 4; j++)
        t[ty + j * 8][tx] = g_v[(size_t)(b * T_ + s0 + ty + j * 8) * 2048 + h * 128 + v0 + tx];
    __syncthreads();
#pragma unroll
    for (int j = 0; j < 4; j++) {
        const int v = v0 + ty + j * 8;
        const float x = t[tx][ty + j * 8];
        const uint16_t hi = f2bf(x);
        const uint16_t lo = f2bf(x - bf2f(hi));
        uint16_t* o = g_vt2 + ((size_t)bh * 128 + v) * 4096 + s0 + tx;
        o[0]    = hi;
        o[2048] = lo;
    }
}

// ---------------------------------------------------------------------------
// Baseline-ISA tensor core helpers
// ---------------------------------------------------------------------------
__device__ __forceinline__ uint32_t smem_u32(const void* p) {
    uint32_t a;
    asm("{ .reg .u64 t; cvta.to.shared.u64 t, %1; cvt.u32.u64 %0, t; }" : "=r"(a) : "l"(p));
    return a;
}
__device__ __forceinline__ void cp_async16(uint32_t dst, const void* src) {
    asm volatile("cp.async.cg.shared.global [%0], [%1], 16;" :: "r"(dst), "l"(src));
}
__device__ __forceinline__ void cp_commit() {
    asm volatile("cp.async.commit_group;" ::: "memory");
}
template <int N>
__device__ __forceinline__ void cp_wait() {
    asm volatile("cp.async.wait_group %0;" :: "n"(N) : "memory");
}
__device__ __forceinline__ void ldmatrix_x4(uint32_t* r, uint32_t addr) {
    asm volatile("ldmatrix.sync.aligned.m8n8.x4.shared.b16 {%0,%1,%2,%3}, [%4];"
                 : "=r"(r[0]), "=r"(r[1]), "=r"(r[2]), "=r"(r[3]) : "r"(addr));
}
__device__ __forceinline__ void mma16816(float* d, const uint32_t* a, uint32_t b0, uint32_t b1) {
    asm volatile(
        "mma.sync.aligned.m16n8k16.row.col.f32.bf16.bf16.f32 "
        "{%0,%1,%2,%3}, {%4,%5,%6,%7}, {%8,%9}, {%0,%1,%2,%3};"
        : "+f"(d[0]), "+f"(d[1]), "+f"(d[2]), "+f"(d[3])
        : "r"(a[0]), "r"(a[1]), "r"(a[2]), "r"(a[3]), "r"(b0), "r"(b1));
}

// ---------------------------------------------------------------------------
// GEMM body (bf16x3 over [hi|lo]) -- R9-proven config, unchanged.
// ---------------------------------------------------------------------------
#define GEMM_SMEM_BYTES (3 * 2 * 16384)   // 96 KB

__device__ __forceinline__ void
gemm_body(const uint16_t* __restrict__ A2, const uint16_t* __restrict__ B2,
          const float* __restrict__ bias, float* __restrict__ Cm,
          int K, int N, int mode)
{
    extern __shared__ __align__(128) char smx[];
    const uint32_t sb = smem_u32(smx);

    const int tid = threadIdx.x;
    const int wid = tid >> 5;
    const int lid = tid & 31;
    const int m0 = blockIdx.y * 128;
    const int n0 = blockIdx.x * 128;
    const int wm = (wid & 1) * 64;
    const int wn = (wid >> 1) * 32;
    const int KC = K >> 6;
    const int NC = 3 * KC;
    const int K2 = 2 * K;

    float acc[4][4][4];
#pragma unroll
    for (int i = 0; i < 4; i++)
#pragma unroll
        for (int j = 0; j < 4; j++)
#pragma unroll
            for (int r = 0; r < 4; r++) acc[i][j][r] = 0.f;

    auto issue = [&](int c, int s) {
        const int kseg = (c >= 2 * KC) ? 2 : (c >= KC ? 1 : 0);
        const int kin  = c - kseg * KC;
        const int aCol = ((kseg == 2) ? K : 0) + kin * 64;
        const int bCol = ((kseg == 1) ? K : 0) + kin * 64;
        const uint32_t stA = sb + s * 32768;
        const uint32_t stB = stA + 16384;
#pragma unroll
        for (int it = 0; it < 4; it++) {
            const int unit = tid + it * 256;
            const int row  = unit >> 3;
            const int u    = unit & 7;
            const uint32_t off = row * 128 + ((u ^ (row & 7)) * 16);
            cp_async16(stA + off, A2 + (size_t)(m0 + row) * K2 + aCol + u * 8);
            cp_async16(stB + off, B2 + (size_t)(n0 + row) * K2 + bCol + u * 8);
        }
        cp_commit();
    };

    issue(0, 0);
    issue(1, 1);

    int s = 0;
    for (int c = 0; c < NC; ++c) {
        if (c + 2 < NC)      { issue(c + 2, (c + 2) % 3); cp_wait<2>(); }
        else if (c + 1 < NC) { cp_wait<1>(); }
        else                 { cp_wait<0>(); }
        __syncthreads();

        const uint32_t aB = sb + s * 32768;
        const uint32_t bB = aB + 16384;

#pragma unroll
        for (int ks = 0; ks < 4; ks++) {
            const int q = lid >> 3;
            const int l7 = lid & 7;

            uint32_t af[4][4];
#pragma unroll
            for (int mt = 0; mt < 4; mt++) {
                const int row = wm + mt * 16 + (q & 1) * 8 + l7;
                const int su  = (ks * 2 + (q >> 1)) ^ (row & 7);
                ldmatrix_x4(af[mt], aB + row * 128 + su * 16);
            }
            uint32_t bf[2][4];
#pragma unroll
            for (int np = 0; np < 2; np++) {
                const int row = wn + np * 16 + (q >> 1) * 8 + l7;
                const int su  = (ks * 2 + (q & 1)) ^ (row & 7);
                ldmatrix_x4(bf[np], bB + row * 128 + su * 16);
            }
#pragma unroll
            for (int mt = 0; mt < 4; mt++)
#pragma unroll
                for (int nt = 0; nt < 4; nt++)
                    mma16816(acc[mt][nt], af[mt],
                             bf[nt >> 1][(nt & 1) * 2], bf[nt >> 1][(nt & 1) * 2 + 1]);
        }
        __syncthreads();
        s = (s + 1) % 3;
    }

    const int gr = lid >> 2;
    const int gc = (lid & 3) * 2;
#pragma unroll
    for (int mt = 0; mt < 4; mt++) {
        const int row = m0 + wm + mt * 16 + gr;
#pragma unroll
        for (int nt = 0; nt < 4; nt++) {
            const int col = n0 + wn + nt * 8 + gc;
            const float b0 = __ldg(&bias[col]);
            const float b1 = __ldg(&bias[col + 1]);
            float v00 = acc[mt][nt][0] + b0;
            float v01 = acc[mt][nt][1] + b1;
            float v10 = acc[mt][nt][2] + b0;
            float v11 = acc[mt][nt][3] + b1;
            if (mode == 0) {
                *(float2*)(Cm + (size_t)row * N + col)       = make_float2(v00, v01);
                *(float2*)(Cm + (size_t)(row + 8) * N + col) = make_float2(v10, v11);
            } else {
                const bool isq = (col < 1024);
                const int  cl  = isq ? col : (col - 1024);
                const int  h   = cl >> 6;
                const int  d   = cl & 63;
                uint16_t* dst = isq ? g_q2 : g_k2;
#pragma unroll
                for (int rp = 0; rp < 2; rp++) {
                    const int r = row + rp * 8;
                    const float vx = rp ? v10 : v00;
                    const float vy = rp ? v11 : v01;
                    const int b  = r >> 11;
                    const int t  = r & 2047;
                    const size_t base = ((size_t)(b * H_ + h) * T_ + t) * 128 + d;
                    const uint16_t hx = f2bf(vx), hy = f2bf(vy);
                    const uint16_t lx = f2bf(vx - bf2f(hx)), ly = f2bf(vy - bf2f(hy));
                    *(uint32_t*)(dst + base)      = (uint32_t)hx | ((uint32_t)hy << 16);
                    *(uint32_t*)(dst + base + 64) = (uint32_t)lx | ((uint32_t)ly << 16);
                }
            }
        }
    }
}

// Merged projection GEMMs: grid (16, 32, 3); z=0 qk (split epi), z=1 v, z=2 g
__global__ void __launch_bounds__(256)
gemm_proj(const float* __restrict__ b_qk, const float* __restrict__ b_v,
          const float* __restrict__ b_g)
{
    const int z = blockIdx.z;
    if (z == 0)      gemm_body(g_x2, g_wqk2, b_qk, nullptr, 1024, 2048, 1);
    else if (z == 1) gemm_body(g_x2, g_wv2,  b_v,  g_v,     1024, 2048, 0);
    else             gemm_body(g_x2, g_wg2,  b_g,  g_g,     1024, 2048, 0);
}

__global__ void __launch_bounds__(256)
gemm_out(const float* __restrict__ b_o, float* __restrict__ out)
{
    gemm_body(g_y2, g_wo2, b_o, out, 2048, 1024, 0);
}

// ---------------------------------------------------------------------------
// mma.sync retention attention, register-resident S (FlashAttention-style
// D->A fragment reuse).  No S smem round-trip.  Q fragments hoisted.
// Each warp (m_w, n_w): QK cols n_w*32..+32; SV integrates its own 32 s-cols
// over ALL 128 v (vacc[16][4]); n_w halves combined once at epilogue via the
// (then-dead) K smem region.
// smem: Q 16K | K 2x16K | V 2x32K | rowAbs 256B = 114944 B
// ---------------------------------------------------------------------------
#define AT_SQ   0
#define AT_SK   16384
#define AT_SV   49152
#define AT_RA   114688
#define AT_SMEM 114944
#define OBUF_STRIDE 132   // fp32 elements per row (padded vs 128 for banks)

__global__ void __launch_bounds__(256)
retention_attn_mma()
{
    extern __shared__ __align__(128) char smx[];
    const uint32_t sb = smem_u32(smx);
    float* rowAbsS = (float*)(smx + AT_RA);

    const int tid = threadIdx.x;
    const int wid = tid >> 5;
    const int lid = tid & 31;
    const int q   = lid >> 3;
    const int l7  = lid & 7;
    const int m_w = wid & 3;
    const int n_w = wid >> 2;
    const int gr  = lid >> 2;
    const int gc  = (lid & 3) * 2;

    const int qi = gridDim.x - 1 - blockIdx.x;   // big CTAs first
    const int h  = blockIdx.y;
    const int b  = blockIdx.z;
    const int t0 = qi * 64;
    const int bh = b * H_ + h;

    const float gamma = log1pf(-exp2f(-5.0f - (float)h));
    const float em1g  = expm1f(gamma);

    const int r0 = m_w * 16 + gr;
    const int r1 = r0 + 8;
    float rowfac[2];
#pragma unroll
    for (int hrow = 0; hrow < 2; hrow++) {
        const int rl = r0 + hrow * 8;
        const int t  = t0 + rl;
        const float sc2 = expm1f(gamma * (float)(t + 1)) / em1g;
        rowfac[hrow] = expf(gamma * (float)rl) * rsqrtf(sc2);
    }
    float ecl[4][2];
#pragma unroll
    for (int nt = 0; nt < 4; nt++)
#pragma unroll
        for (int cc = 0; cc < 2; cc++)
            ecl[nt][cc] = expf(-gamma * (float)(n_w * 32 + nt * 8 + gc + cc));

    if (tid < 64) rowAbsS[tid] = 0.f;

    auto issueKV = [&](int kt, int st) {
        const int s0 = kt * 64;
#pragma unroll
        for (int it = 0; it < 4; it++) {
            const int unit = tid + it * 256;
            const int seg = unit >> 9, rem = unit & 511;
            const int row = rem >> 3,  u   = rem & 7;
            cp_async16(sb + AT_SK + st * 16384 + seg * 8192 + row * 128 + ((u ^ (row & 7)) * 16),
                       g_k2 + ((size_t)bh * T_ + s0 + row) * 128 + seg * 64 + u * 8);
        }
#pragma unroll
        for (int it = 0; it < 8; it++) {
            const int unit = tid + it * 256;
            const int seg = unit >> 10, rem = unit & 1023;
            const int row = rem >> 3,   u   = rem & 7;
            cp_async16(sb + AT_SV + st * 32768 + seg * 16384 + row * 128 + ((u ^ (row & 7)) * 16),
                       g_vt2 + ((size_t)bh * 128 + row) * 4096 + seg * 2048 + s0 + u * 8);
        }
        cp_commit();
    };

    // prologue: Q (own group) + KV tile 0
    {
#pragma unroll
        for (int it = 0; it < 4; it++) {
            const int unit = tid + it * 256;
            const int seg = unit >> 9, rem = unit & 511;
            const int row = rem >> 3,  u   = rem & 7;
            cp_async16(sb + AT_SQ + seg * 8192 + row * 128 + ((u ^ (row & 7)) * 16),
                       g_q2 + ((size_t)bh * T_ + t0 + row) * 128 + seg * 64 + u * 8);
        }
        cp_commit();
        issueKV(0, 0);
    }

    // Wait for Q (leave KV0 pending), then hoist Q hi/lo fragments to regs.
    cp_wait<1>();
    __syncthreads();
    uint32_t qfh[4][4], qfl[4][4];
#pragma unroll
    for (int ks = 0; ks < 4; ks++) {
        const int row = m_w * 16 + (q & 1) * 8 + l7;
        const int su  = (ks * 2 + (q >> 1)) ^ (row & 7);
        ldmatrix_x4(qfh[ks], sb + AT_SQ + row * 128 + su * 16);
        ldmatrix_x4(qfl[ks], sb + AT_SQ + 8192 + row * 128 + su * 16);
    }

    float vacc[16][4];
#pragma unroll
    for (int i = 0; i < 16; i++)
#pragma unroll
        for (int r = 0; r < 4; r++) vacc[i][r] = 0.f;

    for (int kt = 0; kt <= qi; kt++) {
        const int s0 = kt * 64;
        const int st = kt & 1;
        if (kt < qi) { issueKV(kt + 1, st ^ 1); cp_wait<1>(); }
        else         { cp_wait<0>(); }
        __syncthreads();

        // ---- QK^T (A-side from registers) ----
        float sacc[4][4];
#pragma unroll
        for (int i = 0; i < 4; i++)
#pragma unroll
            for (int r = 0; r < 4; r++) sacc[i][r] = 0.f;

#pragma unroll
        for (int c = 0; c < 3; c++) {
            const uint32_t bB = sb + AT_SK + st * 16384 + ((c == 1) ? 8192 : 0);
#pragma unroll
            for (int ks = 0; ks < 4; ks++) {
                const uint32_t* af = (c == 2) ? qfl[ks] : qfh[ks];
                uint32_t bf[2][4];
#pragma unroll
                for (int np = 0; np < 2; np++) {
                    const int row = n_w * 32 + np * 16 + (q >> 1) * 8 + l7;
                    const int su  = (ks * 2 + (q & 1)) ^ (row & 7);
                    ldmatrix_x4(bf[np], bB + row * 128 + su * 16);
                }
#pragma unroll
                for (int nt = 0; nt < 4; nt++)
                    mma16816(sacc[nt], af,
                             bf[nt >> 1][(nt & 1) * 2], bf[nt >> 1][(nt & 1) * 2 + 1]);
            }
        }

        // ---- mask/decay, rowAbs, pack S directly into A-fragments ----
        const float e_ts = expf(gamma * (float)(t0 - s0));
        const bool diag = (s0 == t0);
        float pa[2] = {0.f, 0.f};
        uint32_t sfh[2][4], sfl[2][4];    // [ksv][frag-reg]
#pragma unroll
        for (int nt = 0; nt < 4; nt++) {
#pragma unroll
            for (int hrow = 0; hrow < 2; hrow++) {
                const int rl = r0 + hrow * 8;
                uint16_t hi[2], lo[2];
#pragma unroll
                for (int cc = 0; cc < 2; cc++) {
                    const int cl = n_w * 32 + nt * 8 + gc + cc;
                    float v = sacc[nt][hrow * 2 + cc] * rowfac[hrow] * (e_ts * ecl[nt][cc]);
                    if (diag && cl > rl) v = 0.f;
                    pa[hrow] += fabsf(v);
                    hi[cc] = f2bf(v);
                    lo[cc] = f2bf(v - bf2f(hi[cc]));
                }
                // A-fragment slot: ksv = nt>>1, reg = (nt&1)*2 + hrow
                sfh[nt >> 1][(nt & 1) * 2 + hrow] = (uint32_t)hi[0] | ((uint32_t)hi[1] << 16);
                sfl[nt >> 1][(nt & 1) * 2 + hrow] = (uint32_t)lo[0] | ((uint32_t)lo[1] << 16);
            }
        }
        pa[0] += __shfl_xor_sync(0xffffffffu, pa[0], 1);
        pa[0] += __shfl_xor_sync(0xffffffffu, pa[0], 2);
        pa[1] += __shfl_xor_sync(0xffffffffu, pa[1], 1);
        pa[1] += __shfl_xor_sync(0xffffffffu, pa[1], 2);
        if ((lid & 3) == 0) {
            atomicAdd(&rowAbsS[r0], pa[0]);
            atomicAdd(&rowAbsS[r1], pa[1]);
        }

        // ---- S @ V (A from registers; warp's k = its own 32 s-cols) ----
#pragma unroll
        for (int c = 0; c < 3; c++) {
            const uint32_t bB = sb + AT_SV + st * 32768 + ((c == 1) ? 16384 : 0);
#pragma unroll
            for (int ksv = 0; ksv < 2; ksv++) {
                const uint32_t* af = (c == 2) ? sfl[ksv] : sfh[ksv];
                uint32_t bf[8][4];
#pragma unroll
                for (int np = 0; np < 8; np++) {
                    const int row = np * 16 + (q >> 1) * 8 + l7;
                    const int su  = (n_w * 4 + ksv * 2 + (q & 1)) ^ (row & 7);
                    ldmatrix_x4(bf[np], bB + row * 128 + su * 16);
                }
#pragma unroll
                for (int ntv = 0; ntv < 16; ntv++)
                    mma16816(vacc[ntv], af,
                             bf[ntv >> 1][(ntv & 1) * 2], bf[ntv >> 1][(ntv & 1) * 2 + 1]);
            }
        }
        __syncthreads();
    }

    // ---- epilogue: combine n_w halves via (dead) K smem region ----
    float* Obuf = (float*)(smx + AT_SK);   // 64 x OBUF_STRIDE fp32 (~33 KB, spans K+V dead space)
    if (n_w == 1) {
#pragma unroll
        for (int hrow = 0; hrow < 2; hrow++) {
            const int rl = r0 + hrow * 8;
#pragma unroll
            for (int ntv = 0; ntv < 16; ntv++) {
                *(float2*)&Obuf[rl * OBUF_STRIDE + ntv * 8 + gc] =
                    make_float2(vacc[ntv][hrow * 2 + 0], vacc[ntv][hrow * 2 + 1]);
            }
        }
    }
    __syncthreads();
    if (n_w == 0) {
        const float den0 = fminf(fmaxf(rowAbsS[r0], 1.0f), 50000.0f);
        const float den1 = fminf(fmaxf(rowAbsS[r1], 1.0f), 50000.0f);
        const float inv[2] = {1.0f / den0, 1.0f / den1};

        float o[16][4];
        float ss[2] = {0.f, 0.f};
#pragma unroll
        for (int hrow = 0; hrow < 2; hrow++) {
            const int rl = r0 + hrow * 8;
#pragma unroll
            for (int ntv = 0; ntv < 16; ntv++) {
                const float2 ov = *(const float2*)&Obuf[rl * OBUF_STRIDE + ntv * 8 + gc];
                float x = (vacc[ntv][hrow * 2 + 0] + ov.x) * inv[hrow];
                float y = (vacc[ntv][hrow * 2 + 1] + ov.y) * inv[hrow];
                o[ntv][hrow * 2 + 0] = x;
                o[ntv][hrow * 2 + 1] = y;
                ss[hrow] = fmaf(x, x, fmaf(y, y, ss[hrow]));
            }
        }
        // full row lives within the quad (4 lanes): xor 1,2 completes the sum
        ss[0] += __shfl_xor_sync(0xffffffffu, ss[0], 1);
        ss[0] += __shfl_xor_sync(0xffffffffu, ss[0], 2);
        ss[1] += __shfl_xor_sync(0xffffffffu, ss[1], 1);
        ss[1] += __shfl_xor_sync(0xffffffffu, ss[1], 2);

        float rstd[2];
#pragma unroll
        for (int hrow = 0; hrow < 2; hrow++)
            rstd[hrow] = rsqrtf(ss[hrow] * (1.0f / 128.0f) + 1.1920929e-7f);

#pragma unroll
        for (int hrow = 0; hrow < 2; hrow++) {
            const int rl = r0 + hrow * 8;
            const int t  = t0 + rl;
            const size_t gbase = ((size_t)(b * T_ + t)) * VBD_ + (size_t)h * VD_;
            const size_t ybase = ((size_t)(b * T_ + t)) * 4096 + (size_t)h * VD_;
#pragma unroll
            for (int ntv = 0; ntv < 16; ntv++) {
                const int v = ntv * 8 + gc;
                const float2 gv = *(const float2*)(g_g + gbase + v);
                float ox = o[ntv][hrow * 2 + 0] * rstd[hrow] * gv.x;
                float oy = o[ntv][hrow * 2 + 1] * rstd[hrow] * gv.y;
                uint16_t hx = f2bf(ox), hy = f2bf(oy);
                uint16_t lx = f2bf(ox - bf2f(hx)), ly = f2bf(oy - bf2f(hy));
                *(uint32_t*)(g_y2 + ybase + v)        = (uint32_t)hx | ((uint32_t)hy << 16);
                *(uint32_t*)(g_y2 + ybase + 2048 + v) = (uint32_t)lx | ((uint32_t)ly << 16);
            }
        }
    }
}

// ---------------------------------------------------------------------------
// Launch
// ---------------------------------------------------------------------------
extern "C" void kernel_launch(void* const* d_in, const int* in_sizes, int n_in,
                              void* d_out, int out_size)
{
    const float* x    = (const float*)d_in[0];
    const float* W_qk = (const float*)d_in[1];
    const float* b_qk = (const float*)d_in[2];
    const float* W_v  = (const float*)d_in[3];
    const float* b_v  = (const float*)d_in[4];
    const float* W_g  = (const float*)d_in[5];
    const float* b_g  = (const float*)d_in[6];
    const float* W_o  = (const float*)d_in[7];
    const float* b_o  = (const float*)d_in[8];
    float* out = (float*)d_out;

    uint16_t *x2;
    cudaGetSymbolAddress((void**)&x2, g_x2);
    cudaFuncSetAttribute(gemm_proj,
                         cudaFuncAttributeMaxDynamicSharedMemorySize, GEMM_SMEM_BYTES);
    cudaFuncSetAttribute(gemm_out,
                         cudaFuncAttributeMaxDynamicSharedMemorySize, GEMM_SMEM_BYTES);
    cudaFuncSetAttribute(retention_attn_mma,
                         cudaFuncAttributeMaxDynamicSharedMemorySize, AT_SMEM);

    // --- split/transpose GEMM operands ([hi|lo]) ---
    {
        split_rows<<<(M_ * (C_ / 4) + 255) / 256, 256>>>(x, x2, M_, C_);
        dim3 bt(32, 8);
        split_transpose_all<<<dim3(64, 64, 4), bt>>>(W_qk, W_v, W_g, W_o);
    }

    // --- merged projection GEMMs: CTA 128x128 (z: qk | v | g) ---
    {
        dim3 g(2048 / 128, M_ / 128, 3);
        gemm_proj<<<g, 256, GEMM_SMEM_BYTES>>>(b_qk, b_v, b_g);
    }

    // --- V transpose/split ---
    {
        dim3 bt(32, 8);
        transpose_split_v<<<dim3(T_ / 32, VD_ / 32, B_ * H_), bt>>>();
    }

    // --- attention (register-S; writes g_y2 directly) ---
    {
        dim3 gAttn(T_ / 64, H_, B_);
        retention_attn_mma<<<gAttn, 256, AT_SMEM>>>();
    }

    // --- output GEMM: CTA 128x128 ---
    {
        dim3 g(1024 / 128, M_ / 128);
        gemm_out<<<g, 256, GEMM_SMEM_BYTES>>>(b_o, out);
    }

    (void)in_sizes; (void)n_in; (void)out_size;
}

// round 13
// speedup vs baseline: 1.0341x; 1.0341x over previous
#include <cuda_runtime.h>
#include <cuda_bf16.h>
#include <math.h>
#include <stdint.h>

// Problem constants
#define B_   2
#define T_   2048
#define C_   1024
#define H_   16
#define KD_  64
#define VD_  128
#define VBD_ 2048
#define M_   (B_ * T_)   // 4096 rows

// ---------------------------------------------------------------------------
// Scratch (static device globals -- no allocation allowed)
// ---------------------------------------------------------------------------
__device__ float g_v [(size_t)M_ * 2048];   // [B*T, VBD] (fp32)
__device__ float g_g [(size_t)M_ * 2048];   // [B*T, VBD] gate (fp32)

// bf16 [hi|lo] buffers
__device__ uint16_t g_x2  [(size_t)M_   * 2048];  // x     [4096, 2*1024]
__device__ uint16_t g_wqk2[(size_t)2048 * 2048];  // W_qk^T[2048, 2*1024]
__device__ uint16_t g_wv2 [(size_t)2048 * 2048];  // W_v^T
__device__ uint16_t g_wg2 [(size_t)2048 * 2048];  // W_g^T
__device__ uint16_t g_wo2 [(size_t)1024 * 4096];  // W_o^T [1024, 2*2048]
__device__ uint16_t g_y2  [(size_t)M_   * 4096];  // y     [4096, 2*2048] (attn writes)

// attention operands (head-major, [hi|lo])
__device__ uint16_t g_q2 [(size_t)B_ * H_ * T_ * 128];   // [bh, t, 2*64]
__device__ uint16_t g_k2 [(size_t)B_ * H_ * T_ * 128];   // [bh, t, 2*64]
__device__ uint16_t g_vt2[(size_t)B_ * H_ * VD_ * 4096]; // [bh, v, 2*2048] over s

// ---------------------------------------------------------------------------
// bf16 split helpers
// ---------------------------------------------------------------------------
__device__ __forceinline__ uint16_t f2bf(float x) {
    __nv_bfloat16 h = __float2bfloat16_rn(x);
    return *reinterpret_cast<uint16_t*>(&h);
}
__device__ __forceinline__ float bf2f(uint16_t u) {
    __nv_bfloat16 h = *reinterpret_cast<__nv_bfloat16*>(&u);
    return __bfloat162float(h);
}

// ---------------------------------------------------------------------------
// split_rows: fp32 [R,K] -> bf16 [R,2K] = [hi | lo]
// ---------------------------------------------------------------------------
__global__ void __launch_bounds__(256)
split_rows(const float* __restrict__ in, uint16_t* __restrict__ out, int R, int K)
{
    const int q4 = K >> 2;
    int i = blockIdx.x * blockDim.x + threadIdx.x;
    if (i >= R * q4) return;
    const int m = i / q4, q = i % q4;
    float4 v = *(const float4*)(in + (size_t)m * K + q * 4);
    ushort4 hi, lo;
    hi.x = f2bf(v.x); lo.x = f2bf(v.x - bf2f(hi.x));
    hi.y = f2bf(v.y); lo.y = f2bf(v.y - bf2f(hi.y));
    hi.z = f2bf(v.z); lo.z = f2bf(v.z - bf2f(hi.z));
    hi.w = f2bf(v.w); lo.w = f2bf(v.w - bf2f(hi.w));
    uint16_t* o = out + (size_t)m * 2 * K + q * 4;
    *(ushort4*)(o)     = hi;
    *(ushort4*)(o + K) = lo;
}

// ---------------------------------------------------------------------------
// split_transpose_all: all 4 weights in one launch (grid.z selects)
// ---------------------------------------------------------------------------
__global__ void __launch_bounds__(256)
split_transpose_all(const float* __restrict__ Wqk, const float* __restrict__ Wv,
                    const float* __restrict__ Wg,  const float* __restrict__ Wo)
{
    const int z = blockIdx.z;
    const float* W;
    uint16_t* out;
    int K, N;
    if (z == 0)      { W = Wqk; out = g_wqk2; K = 1024; N = 2048; }
    else if (z == 1) { W = Wv;  out = g_wv2;  K = 1024; N = 2048; }
    else if (z == 2) { W = Wg;  out = g_wg2;  K = 1024; N = 2048; }
    else             { W = Wo;  out = g_wo2;  K = 2048; N = 1024; }

    const int n0 = blockIdx.x * 32, k0 = blockIdx.y * 32;
    if (n0 >= N || k0 >= K) return;

    __shared__ float t[32][33];
    const int tx = threadIdx.x, ty = threadIdx.y;
#pragma unroll
    for (int j = 0; j < 4; j++)
        t[ty + j * 8][tx] = W[(size_t)(k0 + ty + j * 8) * N + n0 + tx];
    __syncthreads();
#pragma unroll
    for (int j = 0; j < 4; j++) {
        const int n = n0 + ty + j * 8;
        const float v = t[tx][ty + j * 8];
        const uint16_t hi = f2bf(v);
        const uint16_t lo = f2bf(v - bf2f(hi));
        uint16_t* o = out + (size_t)n * 2 * K + k0 + tx;
        o[0] = hi;
        o[K] = lo;
    }
}

// ---------------------------------------------------------------------------
// transpose_split_v: g_v [B*T, 2048] -> g_vt2 [bh, v, 2*2048] ([hi|lo] over s)
// ---------------------------------------------------------------------------
__global__ void __launch_bounds__(256)
transpose_split_v()
{
    __shared__ float t[32][33];
    const int tx = threadIdx.x, ty = threadIdx.y;
    const int s0 = blockIdx.x * 32;
    const int v0 = blockIdx.y * 32;
    const int bh = blockIdx.z;
    const int b  = bh >> 4;
    const int h  = bh & 15;
#pragma unroll
    for (int j = 0; j < 4; j++)
        t[ty + j * 8][tx] = g_v[(size_t)(b * T_ + s0 + ty + j * 8) * 2048 + h * 128 + v0 + tx];
    __syncthreads();
#pragma unroll
    for (int j = 0; j < 4; j++) {
        const int v = v0 + ty + j * 8;
        const float x = t[tx][ty + j * 8];
        const uint16_t hi = f2bf(x);
        const uint16_t lo = f2bf(x - bf2f(hi));
        uint16_t* o = g_vt2 + ((size_t)bh * 128 + v) * 4096 + s0 + tx;
        o[0]    = hi;
        o[2048] = lo;
    }
}

// ---------------------------------------------------------------------------
// Baseline-ISA tensor core helpers
// ---------------------------------------------------------------------------
__device__ __forceinline__ uint32_t smem_u32(const void* p) {
    uint32_t a;
    asm("{ .reg .u64 t; cvta.to.shared.u64 t, %1; cvt.u32.u64 %0, t; }" : "=r"(a) : "l"(p));
    return a;
}
__device__ __forceinline__ void cp_async16(uint32_t dst, const void* src) {
    asm volatile("cp.async.cg.shared.global [%0], [%1], 16;" :: "r"(dst), "l"(src));
}
__device__ __forceinline__ void cp_commit() {
    asm volatile("cp.async.commit_group;" ::: "memory");
}
template <int N>
__device__ __forceinline__ void cp_wait() {
    asm volatile("cp.async.wait_group %0;" :: "n"(N) : "memory");
}
__device__ __forceinline__ void ldmatrix_x4(uint32_t* r, uint32_t addr) {
    asm volatile("ldmatrix.sync.aligned.m8n8.x4.shared.b16 {%0,%1,%2,%3}, [%4];"
                 : "=r"(r[0]), "=r"(r[1]), "=r"(r[2]), "=r"(r[3]) : "r"(addr));
}
__device__ __forceinline__ void mma16816(float* d, const uint32_t* a, uint32_t b0, uint32_t b1) {
    asm volatile(
        "mma.sync.aligned.m16n8k16.row.col.f32.bf16.bf16.f32 "
        "{%0,%1,%2,%3}, {%4,%5,%6,%7}, {%8,%9}, {%0,%1,%2,%3};"
        : "+f"(d[0]), "+f"(d[1]), "+f"(d[2]), "+f"(d[3])
        : "r"(a[0]), "r"(a[1]), "r"(a[2]), "r"(a[3]), "r"(b0), "r"(b1));
}

// ---------------------------------------------------------------------------
// GEMM body (bf16x3 over [hi|lo]) -- R9-proven config, unchanged.
// ---------------------------------------------------------------------------
#define GEMM_SMEM_BYTES (3 * 2 * 16384)   // 96 KB

__device__ __forceinline__ void
gemm_body(const uint16_t* __restrict__ A2, const uint16_t* __restrict__ B2,
          const float* __restrict__ bias, float* __restrict__ Cm,
          int K, int N, int mode)
{
    extern __shared__ __align__(128) char smx[];
    const uint32_t sb = smem_u32(smx);

    const int tid = threadIdx.x;
    const int wid = tid >> 5;
    const int lid = tid & 31;
    const int m0 = blockIdx.y * 128;
    const int n0 = blockIdx.x * 128;
    const int wm = (wid & 1) * 64;
    const int wn = (wid >> 1) * 32;
    const int KC = K >> 6;
    const int NC = 3 * KC;
    const int K2 = 2 * K;

    float acc[4][4][4];
#pragma unroll
    for (int i = 0; i < 4; i++)
#pragma unroll
        for (int j = 0; j < 4; j++)
#pragma unroll
            for (int r = 0; r < 4; r++) acc[i][j][r] = 0.f;

    auto issue = [&](int c, int s) {
        const int kseg = (c >= 2 * KC) ? 2 : (c >= KC ? 1 : 0);
        const int kin  = c - kseg * KC;
        const int aCol = ((kseg == 2) ? K : 0) + kin * 64;
        const int bCol = ((kseg == 1) ? K : 0) + kin * 64;
        const uint32_t stA = sb + s * 32768;
        const uint32_t stB = stA + 16384;
#pragma unroll
        for (int it = 0; it < 4; it++) {
            const int unit = tid + it * 256;
            const int row  = unit >> 3;
            const int u    = unit & 7;
            const uint32_t off = row * 128 + ((u ^ (row & 7)) * 16);
            cp_async16(stA + off, A2 + (size_t)(m0 + row) * K2 + aCol + u * 8);
            cp_async16(stB + off, B2 + (size_t)(n0 + row) * K2 + bCol + u * 8);
        }
        cp_commit();
    };

    issue(0, 0);
    issue(1, 1);

    int s = 0;
    for (int c = 0; c < NC; ++c) {
        if (c + 2 < NC)      { issue(c + 2, (c + 2) % 3); cp_wait<2>(); }
        else if (c + 1 < NC) { cp_wait<1>(); }
        else                 { cp_wait<0>(); }
        __syncthreads();

        const uint32_t aB = sb + s * 32768;
        const uint32_t bB = aB + 16384;

#pragma unroll
        for (int ks = 0; ks < 4; ks++) {
            const int q = lid >> 3;
            const int l7 = lid & 7;

            uint32_t af[4][4];
#pragma unroll
            for (int mt = 0; mt < 4; mt++) {
                const int row = wm + mt * 16 + (q & 1) * 8 + l7;
                const int su  = (ks * 2 + (q >> 1)) ^ (row & 7);
                ldmatrix_x4(af[mt], aB + row * 128 + su * 16);
            }
            uint32_t bf[2][4];
#pragma unroll
            for (int np = 0; np < 2; np++) {
                const int row = wn + np * 16 + (q >> 1) * 8 + l7;
                const int su  = (ks * 2 + (q & 1)) ^ (row & 7);
                ldmatrix_x4(bf[np], bB + row * 128 + su * 16);
            }
#pragma unroll
            for (int mt = 0; mt < 4; mt++)
#pragma unroll
                for (int nt = 0; nt < 4; nt++)
                    mma16816(acc[mt][nt], af[mt],
                             bf[nt >> 1][(nt & 1) * 2], bf[nt >> 1][(nt & 1) * 2 + 1]);
        }
        __syncthreads();
        s = (s + 1) % 3;
    }

    const int gr = lid >> 2;
    const int gc = (lid & 3) * 2;
#pragma unroll
    for (int mt = 0; mt < 4; mt++) {
        const int row = m0 + wm + mt * 16 + gr;
#pragma unroll
        for (int nt = 0; nt < 4; nt++) {
            const int col = n0 + wn + nt * 8 + gc;
            const float b0 = __ldg(&bias[col]);
            const float b1 = __ldg(&bias[col + 1]);
            float v00 = acc[mt][nt][0] + b0;
            float v01 = acc[mt][nt][1] + b1;
            float v10 = acc[mt][nt][2] + b0;
            float v11 = acc[mt][nt][3] + b1;
            if (mode == 0) {
                *(float2*)(Cm + (size_t)row * N + col)       = make_float2(v00, v01);
                *(float2*)(Cm + (size_t)(row + 8) * N + col) = make_float2(v10, v11);
            } else {
                const bool isq = (col < 1024);
                const int  cl  = isq ? col : (col - 1024);
                const int  h   = cl >> 6;
                const int  d   = cl & 63;
                uint16_t* dst = isq ? g_q2 : g_k2;
#pragma unroll
                for (int rp = 0; rp < 2; rp++) {
                    const int r = row + rp * 8;
                    const float vx = rp ? v10 : v00;
                    const float vy = rp ? v11 : v01;
                    const int b  = r >> 11;
                    const int t  = r & 2047;
                    const size_t base = ((size_t)(b * H_ + h) * T_ + t) * 128 + d;
                    const uint16_t hx = f2bf(vx), hy = f2bf(vy);
                    const uint16_t lx = f2bf(vx - bf2f(hx)), ly = f2bf(vy - bf2f(hy));
                    *(uint32_t*)(dst + base)      = (uint32_t)hx | ((uint32_t)hy << 16);
                    *(uint32_t*)(dst + base + 64) = (uint32_t)lx | ((uint32_t)ly << 16);
                }
            }
        }
    }
}

// Merged projection GEMMs: grid (16, 32, 3); z=0 qk (split epi), z=1 v, z=2 g
__global__ void __launch_bounds__(256)
gemm_proj(const float* __restrict__ b_qk, const float* __restrict__ b_v,
          const float* __restrict__ b_g)
{
    const int z = blockIdx.z;
    if (z == 0)      gemm_body(g_x2, g_wqk2, b_qk, nullptr, 1024, 2048, 1);
    else if (z == 1) gemm_body(g_x2, g_wv2,  b_v,  g_v,     1024, 2048, 0);
    else             gemm_body(g_x2, g_wg2,  b_g,  g_g,     1024, 2048, 0);
}

__global__ void __launch_bounds__(256)
gemm_out(const float* __restrict__ b_o, float* __restrict__ out)
{
    gemm_body(g_y2, g_wo2, b_o, out, 2048, 1024, 0);
}

// ---------------------------------------------------------------------------
// mma.sync retention attention ([hi|lo], 3-term virtual loop), fused
// RMSNorm + gating; writes g_y2 directly.   R11 structure (S via smem,
// vacc[8][4], syncwarp) + Q fragments hoisted to registers.
// smem: Q 16K | S 16K | K 2x16K | V 2x32K | reductions = 131840 B
// ---------------------------------------------------------------------------
#define AT_SQ   0
#define AT_SS   16384
#define AT_SK   32768
#define AT_SV   65536
#define AT_RA   131072
#define AT_RS   131328
#define AT_SMEM 131840

__global__ void __launch_bounds__(256)
retention_attn_mma()
{
    extern __shared__ __align__(128) char smx[];
    const uint32_t sb = smem_u32(smx);
    float* rowAbsS = (float*)(smx + AT_RA);
    float* rssS    = (float*)(smx + AT_RS);

    const int tid = threadIdx.x;
    const int wid = tid >> 5;
    const int lid = tid & 31;
    const int q   = lid >> 3;
    const int l7  = lid & 7;
    const int m_w = wid & 3;
    const int n_w = wid >> 2;
    const int gr  = lid >> 2;
    const int gc  = (lid & 3) * 2;

    const int qi = gridDim.x - 1 - blockIdx.x;   // big CTAs first
    const int h  = blockIdx.y;
    const int b  = blockIdx.z;
    const int t0 = qi * 64;
    const int bh = b * H_ + h;

    const float gamma = log1pf(-exp2f(-5.0f - (float)h));
    const float em1g  = expm1f(gamma);

    const int r0 = m_w * 16 + gr;
    const int r1 = r0 + 8;
    float rowfac[2];
#pragma unroll
    for (int hrow = 0; hrow < 2; hrow++) {
        const int rl = r0 + hrow * 8;
        const int t  = t0 + rl;
        const float sc2 = expm1f(gamma * (float)(t + 1)) / em1g;
        rowfac[hrow] = expf(gamma * (float)rl) * rsqrtf(sc2);
    }
    float ecl[4][2];
#pragma unroll
    for (int nt = 0; nt < 4; nt++)
#pragma unroll
        for (int cc = 0; cc < 2; cc++)
            ecl[nt][cc] = expf(-gamma * (float)(n_w * 32 + nt * 8 + gc + cc));

    if (tid < 64) rowAbsS[tid] = 0.f;

    auto issueKV = [&](int kt, int st) {
        const int s0 = kt * 64;
#pragma unroll
        for (int it = 0; it < 4; it++) {
            const int unit = tid + it * 256;
            const int seg = unit >> 9, rem = unit & 511;
            const int row = rem >> 3,  u   = rem & 7;
            cp_async16(sb + AT_SK + st * 16384 + seg * 8192 + row * 128 + ((u ^ (row & 7)) * 16),
                       g_k2 + ((size_t)bh * T_ + s0 + row) * 128 + seg * 64 + u * 8);
        }
#pragma unroll
        for (int it = 0; it < 8; it++) {
            const int unit = tid + it * 256;
            const int seg = unit >> 10, rem = unit & 1023;
            const int row = rem >> 3,   u   = rem & 7;
            cp_async16(sb + AT_SV + st * 32768 + seg * 16384 + row * 128 + ((u ^ (row & 7)) * 16),
                       g_vt2 + ((size_t)bh * 128 + row) * 4096 + seg * 2048 + s0 + u * 8);
        }
        cp_commit();
    };

    // prologue: Q (own group) + KV tile 0
    {
#pragma unroll
        for (int it = 0; it < 4; it++) {
            const int unit = tid + it * 256;
            const int seg = unit >> 9, rem = unit & 511;
            const int row = rem >> 3,  u   = rem & 7;
            cp_async16(sb + AT_SQ + seg * 8192 + row * 128 + ((u ^ (row & 7)) * 16),
                       g_q2 + ((size_t)bh * T_ + t0 + row) * 128 + seg * 64 + u * 8);
        }
        cp_commit();
        issueKV(0, 0);
    }

    // Wait for Q group (leave KV0 pending), hoist Q hi/lo fragments to regs.
    cp_wait<1>();
    __syncthreads();
    uint32_t qfh[4][4], qfl[4][4];
#pragma unroll
    for (int ks = 0; ks < 4; ks++) {
        const int row = m_w * 16 + (q & 1) * 8 + l7;
        const int su  = (ks * 2 + (q >> 1)) ^ (row & 7);
        ldmatrix_x4(qfh[ks], sb + AT_SQ + row * 128 + su * 16);
        ldmatrix_x4(qfl[ks], sb + AT_SQ + 8192 + row * 128 + su * 16);
    }

    float vacc[8][4];
#pragma unroll
    for (int i = 0; i < 8; i++)
#pragma unroll
        for (int r = 0; r < 4; r++) vacc[i][r] = 0.f;

    for (int kt = 0; kt <= qi; kt++) {
        const int s0 = kt * 64;
        const int st = kt & 1;
        if (kt < qi) { issueKV(kt + 1, st ^ 1); cp_wait<1>(); }
        else         { cp_wait<0>(); }
        __syncthreads();

        // ---- QK^T (A-side from registers) ----
        float sacc[4][4];
#pragma unroll
        for (int i = 0; i < 4; i++)
#pragma unroll
            for (int r = 0; r < 4; r++) sacc[i][r] = 0.f;

#pragma unroll
        for (int c = 0; c < 3; c++) {
            const uint32_t bB = sb + AT_SK + st * 16384 + ((c == 1) ? 8192 : 0);
#pragma unroll
            for (int ks = 0; ks < 4; ks++) {
                const uint32_t* af = (c == 2) ? qfl[ks] : qfh[ks];
                uint32_t bf[2][4];
#pragma unroll
                for (int np = 0; np < 2; np++) {
                    const int row = n_w * 32 + np * 16 + (q >> 1) * 8 + l7;
                    const int su  = (ks * 2 + (q & 1)) ^ (row & 7);
                    ldmatrix_x4(bf[np], bB + row * 128 + su * 16);
                }
#pragma unroll
                for (int nt = 0; nt < 4; nt++)
                    mma16816(sacc[nt], af,
                             bf[nt >> 1][(nt & 1) * 2], bf[nt >> 1][(nt & 1) * 2 + 1]);
            }
        }

        // ---- mask/decay, rowAbs, convert -> S [hi|lo] (warp-local rows) ----
        const float e_ts = expf(gamma * (float)(t0 - s0));
        const bool diag = (s0 == t0);
        float pa[2] = {0.f, 0.f};
#pragma unroll
        for (int nt = 0; nt < 4; nt++) {
#pragma unroll
            for (int hrow = 0; hrow < 2; hrow++) {
                const int rl = r0 + hrow * 8;
                uint16_t hi[2], lo[2];
#pragma unroll
                for (int cc = 0; cc < 2; cc++) {
                    const int cl = n_w * 32 + nt * 8 + gc + cc;
                    float v = sacc[nt][hrow * 2 + cc] * rowfac[hrow] * (e_ts * ecl[nt][cc]);
                    if (diag && cl > rl) v = 0.f;
                    pa[hrow] += fabsf(v);
                    hi[cc] = f2bf(v);
                    lo[cc] = f2bf(v - bf2f(hi[cc]));
                }
                const int cl0 = n_w * 32 + nt * 8 + gc;
                const uint32_t hp = (uint32_t)hi[0] | ((uint32_t)hi[1] << 16);
                const uint32_t lp = (uint32_t)lo[0] | ((uint32_t)lo[1] << 16);
                const uint32_t byo = rl * 128 + (((cl0 >> 3) ^ (rl & 7)) * 16) + (cl0 & 7) * 2;
                *(uint32_t*)(smx + AT_SS + byo)        = hp;
                *(uint32_t*)(smx + AT_SS + 8192 + byo) = lp;
            }
        }
        pa[0] += __shfl_xor_sync(0xffffffffu, pa[0], 1);
        pa[0] += __shfl_xor_sync(0xffffffffu, pa[0], 2);
        pa[1] += __shfl_xor_sync(0xffffffffu, pa[1], 1);
        pa[1] += __shfl_xor_sync(0xffffffffu, pa[1], 2);
        if ((lid & 3) == 0) {
            atomicAdd(&rowAbsS[r0], pa[0]);
            atomicAdd(&rowAbsS[r1], pa[1]);
        }
        // S rows are produced and consumed by the SAME warp; warp-local
        // visibility suffices.
        __syncwarp();

        // ---- S @ V ----
#pragma unroll
        for (int c = 0; c < 3; c++) {
            const uint32_t aB = sb + AT_SS + ((c == 2) ? 8192 : 0);
            const uint32_t bB = sb + AT_SV + st * 32768 + ((c == 1) ? 16384 : 0);
#pragma unroll
            for (int ks = 0; ks < 4; ks++) {
                uint32_t af[4];
                {
                    const int row = m_w * 16 + (q & 1) * 8 + l7;
                    const int su  = (ks * 2 + (q >> 1)) ^ (row & 7);
                    ldmatrix_x4(af, aB + row * 128 + su * 16);
                }
                uint32_t bf[4][4];
#pragma unroll
                for (int np = 0; np < 4; np++) {
                    const int row = n_w * 64 + np * 16 + (q >> 1) * 8 + l7;
                    const int su  = (ks * 2 + (q & 1)) ^ (row & 7);
                    ldmatrix_x4(bf[np], bB + row * 128 + su * 16);
                }
#pragma unroll
                for (int nt = 0; nt < 8; nt++)
                    mma16816(vacc[nt], af,
                             bf[nt >> 1][(nt & 1) * 2], bf[nt >> 1][(nt & 1) * 2 + 1]);
            }
        }
        __syncthreads();
    }

    // ---- epilogue ----
    const float den0 = fminf(fmaxf(rowAbsS[r0], 1.0f), 50000.0f);
    const float den1 = fminf(fmaxf(rowAbsS[r1], 1.0f), 50000.0f);
    const float inv[2] = {1.0f / den0, 1.0f / den1};

    float ss[2] = {0.f, 0.f};
#pragma unroll
    for (int nt = 0; nt < 8; nt++)
#pragma unroll
        for (int hrow = 0; hrow < 2; hrow++)
#pragma unroll
            for (int cc = 0; cc < 2; cc++) {
                const float o = vacc[nt][hrow * 2 + cc] * inv[hrow];
                ss[hrow] = fmaf(o, o, ss[hrow]);
            }
    ss[0] += __shfl_xor_sync(0xffffffffu, ss[0], 1);
    ss[0] += __shfl_xor_sync(0xffffffffu, ss[0], 2);
    ss[1] += __shfl_xor_sync(0xffffffffu, ss[1], 1);
    ss[1] += __shfl_xor_sync(0xffffffffu, ss[1], 2);
    if ((lid & 3) == 0) {
        rssS[r0 * 2 + n_w] = ss[0];
        rssS[r1 * 2 + n_w] = ss[1];
    }
    __syncthreads();

    float rstd[2];
#pragma unroll
    for (int hrow = 0; hrow < 2; hrow++) {
        const int rl = r0 + hrow * 8;
        rstd[hrow] = rsqrtf((rssS[rl * 2] + rssS[rl * 2 + 1]) * (1.0f / 128.0f)
                            + 1.1920929e-7f);
    }

#pragma unroll
    for (int hrow = 0; hrow < 2; hrow++) {
        const int rl = r0 + hrow * 8;
        const int t  = t0 + rl;
        const size_t gbase = ((size_t)(b * T_ + t)) * VBD_ + (size_t)h * VD_;
        const size_t ybase = ((size_t)(b * T_ + t)) * 4096 + (size_t)h * VD_;
#pragma unroll
        for (int nt = 0; nt < 8; nt++) {
            const int v = n_w * 64 + nt * 8 + gc;
            const float2 gv = *(const float2*)(g_g + gbase + v);
            float ox = vacc[nt][hrow * 2 + 0] * inv[hrow] * rstd[hrow] * gv.x;
            float oy = vacc[nt][hrow * 2 + 1] * inv[hrow] * rstd[hrow] * gv.y;
            uint16_t hx = f2bf(ox), hy = f2bf(oy);
            uint16_t lx = f2bf(ox - bf2f(hx)), ly = f2bf(oy - bf2f(hy));
            *(uint32_t*)(g_y2 + ybase + v)        = (uint32_t)hx | ((uint32_t)hy << 16);
            *(uint32_t*)(g_y2 + ybase + 2048 + v) = (uint32_t)lx | ((uint32_t)ly << 16);
        }
    }
}

// ---------------------------------------------------------------------------
// Launch
// ---------------------------------------------------------------------------
extern "C" void kernel_launch(void* const* d_in, const int* in_sizes, int n_in,
                              void* d_out, int out_size)
{
    const float* x    = (const float*)d_in[0];
    const float* W_qk = (const float*)d_in[1];
    const float* b_qk = (const float*)d_in[2];
    const float* W_v  = (const float*)d_in[3];
    const float* b_v  = (const float*)d_in[4];
    const float* W_g  = (const float*)d_in[5];
    const float* b_g  = (const float*)d_in[6];
    const float* W_o  = (const float*)d_in[7];
    const float* b_o  = (const float*)d_in[8];
    float* out = (float*)d_out;

    uint16_t *x2;
    cudaGetSymbolAddress((void**)&x2, g_x2);
    cudaFuncSetAttribute(gemm_proj,
                         cudaFuncAttributeMaxDynamicSharedMemorySize, GEMM_SMEM_BYTES);
    cudaFuncSetAttribute(gemm_out,
                         cudaFuncAttributeMaxDynamicSharedMemorySize, GEMM_SMEM_BYTES);
    cudaFuncSetAttribute(retention_attn_mma,
                         cudaFuncAttributeMaxDynamicSharedMemorySize, AT_SMEM);

    // --- split/transpose GEMM operands ([hi|lo]) ---
    {
        split_rows<<<(M_ * (C_ / 4) + 255) / 256, 256>>>(x, x2, M_, C_);
        dim3 bt(32, 8);
        split_transpose_all<<<dim3(64, 64, 4), bt>>>(W_qk, W_v, W_g, W_o);
    }

    // --- merged projection GEMMs: CTA 128x128 (z: qk | v | g) ---
    {
        dim3 g(2048 / 128, M_ / 128, 3);
        gemm_proj<<<g, 256, GEMM_SMEM_BYTES>>>(b_qk, b_v, b_g);
    }

    // --- V transpose/split ---
    {
        dim3 bt(32, 8);
        transpose_split_v<<<dim3(T_ / 32, VD_ / 32, B_ * H_), bt>>>();
    }

    // --- attention (R11 pipeline + hoisted Q frags; writes g_y2) ---
    {
        dim3 gAttn(T_ / 64, H_, B_);
        retention_attn_mma<<<gAttn, 256, AT_SMEM>>>();
    }

    // --- output GEMM: CTA 128x128 ---
    {
        dim3 g(1024 / 128, M_ / 128);
        gemm_out<<<g, 256, GEMM_SMEM_BYTES>>>(b_o, out);
    }

    (void)in_sizes; (void)n_in; (void)out_size;
}

// round 14
// speedup vs baseline: 1.0520x; 1.0174x over previous
#include <cuda_runtime.h>
#include <cuda_bf16.h>
#include <math.h>
#include <stdint.h>

// Problem constants
#define B_   2
#define T_   2048
#define C_   1024
#define H_   16
#define KD_  64
#define VD_  128
#define VBD_ 2048
#define M_   (B_ * T_)   // 4096 rows

// ---------------------------------------------------------------------------
// Scratch (static device globals -- no allocation allowed)
// ---------------------------------------------------------------------------
__device__ float g_v [(size_t)M_ * 2048];   // [B*T, VBD] (fp32)
__device__ float g_g [(size_t)M_ * 2048];   // [B*T, VBD] gate (fp32)

// bf16 [hi|lo] buffers
__device__ uint16_t g_x2  [(size_t)M_   * 2048];  // x     [4096, 2*1024]
__device__ uint16_t g_wqk2[(size_t)2048 * 2048];  // W_qk^T[2048, 2*1024]
__device__ uint16_t g_wv2 [(size_t)2048 * 2048];  // W_v^T
__device__ uint16_t g_wg2 [(size_t)2048 * 2048];  // W_g^T
__device__ uint16_t g_wo2 [(size_t)1024 * 4096];  // W_o^T [1024, 2*2048]
__device__ uint16_t g_y2  [(size_t)M_   * 4096];  // y     [4096, 2*2048] (attn writes)

// attention operands (head-major, [hi|lo])
__device__ uint16_t g_q2 [(size_t)B_ * H_ * T_ * 128];   // [bh, t, 2*64]
__device__ uint16_t g_k2 [(size_t)B_ * H_ * T_ * 128];   // [bh, t, 2*64]
__device__ uint16_t g_vt2[(size_t)B_ * H_ * VD_ * 4096]; // [bh, v, 2*2048] over s

// ---------------------------------------------------------------------------
// bf16 split helpers
// ---------------------------------------------------------------------------
__device__ __forceinline__ uint16_t f2bf(float x) {
    __nv_bfloat16 h = __float2bfloat16_rn(x);
    return *reinterpret_cast<uint16_t*>(&h);
}
__device__ __forceinline__ float bf2f(uint16_t u) {
    __nv_bfloat16 h = *reinterpret_cast<__nv_bfloat16*>(&u);
    return __bfloat162float(h);
}

// ---------------------------------------------------------------------------
// split_rows: fp32 [R,K] -> bf16 [R,2K] = [hi | lo]
// ---------------------------------------------------------------------------
__global__ void __launch_bounds__(256)
split_rows(const float* __restrict__ in, uint16_t* __restrict__ out, int R, int K)
{
    const int q4 = K >> 2;
    int i = blockIdx.x * blockDim.x + threadIdx.x;
    if (i >= R * q4) return;
    const int m = i / q4, q = i % q4;
    float4 v = *(const float4*)(in + (size_t)m * K + q * 4);
    ushort4 hi, lo;
    hi.x = f2bf(v.x); lo.x = f2bf(v.x - bf2f(hi.x));
    hi.y = f2bf(v.y); lo.y = f2bf(v.y - bf2f(hi.y));
    hi.z = f2bf(v.z); lo.z = f2bf(v.z - bf2f(hi.z));
    hi.w = f2bf(v.w); lo.w = f2bf(v.w - bf2f(hi.w));
    uint16_t* o = out + (size_t)m * 2 * K + q * 4;
    *(ushort4*)(o)     = hi;
    *(ushort4*)(o + K) = lo;
}

// ---------------------------------------------------------------------------
// split_transpose_all: all 4 weights in one launch (grid.z selects)
// ---------------------------------------------------------------------------
__global__ void __launch_bounds__(256)
split_transpose_all(const float* __restrict__ Wqk, const float* __restrict__ Wv,
                    const float* __restrict__ Wg,  const float* __restrict__ Wo)
{
    const int z = blockIdx.z;
    const float* W;
    uint16_t* out;
    int K, N;
    if (z == 0)      { W = Wqk; out = g_wqk2; K = 1024; N = 2048; }
    else if (z == 1) { W = Wv;  out = g_wv2;  K = 1024; N = 2048; }
    else if (z == 2) { W = Wg;  out = g_wg2;  K = 1024; N = 2048; }
    else             { W = Wo;  out = g_wo2;  K = 2048; N = 1024; }

    const int n0 = blockIdx.x * 32, k0 = blockIdx.y * 32;
    if (n0 >= N || k0 >= K) return;

    __shared__ float t[32][33];
    const int tx = threadIdx.x, ty = threadIdx.y;
#pragma unroll
    for (int j = 0; j < 4; j++)
        t[ty + j * 8][tx] = W[(size_t)(k0 + ty + j * 8) * N + n0 + tx];
    __syncthreads();
#pragma unroll
    for (int j = 0; j < 4; j++) {
        const int n = n0 + ty + j * 8;
        const float v = t[tx][ty + j * 8];
        const uint16_t hi = f2bf(v);
        const uint16_t lo = f2bf(v - bf2f(hi));
        uint16_t* o = out + (size_t)n * 2 * K + k0 + tx;
        o[0] = hi;
        o[K] = lo;
    }
}

// ---------------------------------------------------------------------------
// transpose_split_v: g_v [B*T, 2048] -> g_vt2 [bh, v, 2*2048] ([hi|lo] over s)
// ---------------------------------------------------------------------------
__global__ void __launch_bounds__(256)
transpose_split_v()
{
    __shared__ float t[32][33];
    const int tx = threadIdx.x, ty = threadIdx.y;
    const int s0 = blockIdx.x * 32;
    const int v0 = blockIdx.y * 32;
    const int bh = blockIdx.z;
    const int b  = bh >> 4;
    const int h  = bh & 15;
#pragma unroll
    for (int j = 0; j < 4; j++)
        t[ty + j * 8][tx] = g_v[(size_t)(b * T_ + s0 + ty + j * 8) * 2048 + h * 128 + v0 + tx];
    __syncthreads();
#pragma unroll
    for (int j = 0; j < 4; j++) {
        const int v = v0 + ty + j * 8;
        const float x = t[tx][ty + j * 8];
        const uint16_t hi = f2bf(x);
        const uint16_t lo = f2bf(x - bf2f(hi));
        uint16_t* o = g_vt2 + ((size_t)bh * 128 + v) * 4096 + s0 + tx;
        o[0]    = hi;
        o[2048] = lo;
    }
}

// ---------------------------------------------------------------------------
// Baseline-ISA tensor core helpers
// ---------------------------------------------------------------------------
__device__ __forceinline__ uint32_t smem_u32(const void* p) {
    uint32_t a;
    asm("{ .reg .u64 t; cvta.to.shared.u64 t, %1; cvt.u32.u64 %0, t; }" : "=r"(a) : "l"(p));
    return a;
}
__device__ __forceinline__ void cp_async16(uint32_t dst, const void* src) {
    asm volatile("cp.async.cg.shared.global [%0], [%1], 16;" :: "r"(dst), "l"(src));
}
__device__ __forceinline__ void cp_commit() {
    asm volatile("cp.async.commit_group;" ::: "memory");
}
template <int N>
__device__ __forceinline__ void cp_wait() {
    asm volatile("cp.async.wait_group %0;" :: "n"(N) : "memory");
}
__device__ __forceinline__ void ldmatrix_x4(uint32_t* r, uint32_t addr) {
    asm volatile("ldmatrix.sync.aligned.m8n8.x4.shared.b16 {%0,%1,%2,%3}, [%4];"
                 : "=r"(r[0]), "=r"(r[1]), "=r"(r[2]), "=r"(r[3]) : "r"(addr));
}
__device__ __forceinline__ void mma16816(float* d, const uint32_t* a, uint32_t b0, uint32_t b1) {
    asm volatile(
        "mma.sync.aligned.m16n8k16.row.col.f32.bf16.bf16.f32 "
        "{%0,%1,%2,%3}, {%4,%5,%6,%7}, {%8,%9}, {%0,%1,%2,%3};"
        : "+f"(d[0]), "+f"(d[1]), "+f"(d[2]), "+f"(d[3])
        : "r"(a[0]), "r"(a[1]), "r"(a[2]), "r"(a[3]), "r"(b0), "r"(b1));
}

// ---------------------------------------------------------------------------
// GEMM body (bf16x3 over [hi|lo]) -- R9 tile config, single-barrier mainloop:
//   wait<1>; __syncthreads; issue(c+2); compute(c)
// Top sync proves all warps finished c-1, so issuing into stage (c+2)%3
// (= (c-1)%3) is safe; g_{c+2}'s load window stays ~2 compute phases.
// ---------------------------------------------------------------------------
#define GEMM_SMEM_BYTES (3 * 2 * 16384)   // 96 KB

__device__ __forceinline__ void
gemm_body(const uint16_t* __restrict__ A2, const uint16_t* __restrict__ B2,
          const float* __restrict__ bias, float* __restrict__ Cm,
          int K, int N, int mode)
{
    extern __shared__ __align__(128) char smx[];
    const uint32_t sb = smem_u32(smx);

    const int tid = threadIdx.x;
    const int wid = tid >> 5;
    const int lid = tid & 31;
    const int m0 = blockIdx.y * 128;
    const int n0 = blockIdx.x * 128;
    const int wm = (wid & 1) * 64;
    const int wn = (wid >> 1) * 32;
    const int KC = K >> 6;
    const int NC = 3 * KC;
    const int K2 = 2 * K;

    float acc[4][4][4];
#pragma unroll
    for (int i = 0; i < 4; i++)
#pragma unroll
        for (int j = 0; j < 4; j++)
#pragma unroll
            for (int r = 0; r < 4; r++) acc[i][j][r] = 0.f;

    auto issue = [&](int c, int s) {
        const int kseg = (c >= 2 * KC) ? 2 : (c >= KC ? 1 : 0);
        const int kin  = c - kseg * KC;
        const int aCol = ((kseg == 2) ? K : 0) + kin * 64;
        const int bCol = ((kseg == 1) ? K : 0) + kin * 64;
        const uint32_t stA = sb + s * 32768;
        const uint32_t stB = stA + 16384;
#pragma unroll
        for (int it = 0; it < 4; it++) {
            const int unit = tid + it * 256;
            const int row  = unit >> 3;
            const int u    = unit & 7;
            const uint32_t off = row * 128 + ((u ^ (row & 7)) * 16);
            cp_async16(stA + off, A2 + (size_t)(m0 + row) * K2 + aCol + u * 8);
            cp_async16(stB + off, B2 + (size_t)(n0 + row) * K2 + bCol + u * 8);
        }
        cp_commit();
    };

    issue(0, 0);
    issue(1, 1);

    int s = 0;
    for (int c = 0; c < NC; ++c) {
        if (c + 1 < NC) cp_wait<1>();
        else            cp_wait<0>();
        __syncthreads();
        if (c + 2 < NC) issue(c + 2, (c + 2) % 3);

        const uint32_t aB = sb + s * 32768;
        const uint32_t bB = aB + 16384;

#pragma unroll
        for (int ks = 0; ks < 4; ks++) {
            const int q = lid >> 3;
            const int l7 = lid & 7;

            uint32_t af[4][4];
#pragma unroll
            for (int mt = 0; mt < 4; mt++) {
                const int row = wm + mt * 16 + (q & 1) * 8 + l7;
                const int su  = (ks * 2 + (q >> 1)) ^ (row & 7);
                ldmatrix_x4(af[mt], aB + row * 128 + su * 16);
            }
            uint32_t bf[2][4];
#pragma unroll
            for (int np = 0; np < 2; np++) {
                const int row = wn + np * 16 + (q >> 1) * 8 + l7;
                const int su  = (ks * 2 + (q & 1)) ^ (row & 7);
                ldmatrix_x4(bf[np], bB + row * 128 + su * 16);
            }
#pragma unroll
            for (int mt = 0; mt < 4; mt++)
#pragma unroll
                for (int nt = 0; nt < 4; nt++)
                    mma16816(acc[mt][nt], af[mt],
                             bf[nt >> 1][(nt & 1) * 2], bf[nt >> 1][(nt & 1) * 2 + 1]);
        }
        s = (s + 1) % 3;
    }

    const int gr = lid >> 2;
    const int gc = (lid & 3) * 2;
#pragma unroll
    for (int mt = 0; mt < 4; mt++) {
        const int row = m0 + wm + mt * 16 + gr;
#pragma unroll
        for (int nt = 0; nt < 4; nt++) {
            const int col = n0 + wn + nt * 8 + gc;
            const float b0 = __ldg(&bias[col]);
            const float b1 = __ldg(&bias[col + 1]);
            float v00 = acc[mt][nt][0] + b0;
            float v01 = acc[mt][nt][1] + b1;
            float v10 = acc[mt][nt][2] + b0;
            float v11 = acc[mt][nt][3] + b1;
            if (mode == 0) {
                *(float2*)(Cm + (size_t)row * N + col)       = make_float2(v00, v01);
                *(float2*)(Cm + (size_t)(row + 8) * N + col) = make_float2(v10, v11);
            } else {
                const bool isq = (col < 1024);
                const int  cl  = isq ? col : (col - 1024);
                const int  h   = cl >> 6;
                const int  d   = cl & 63;
                uint16_t* dst = isq ? g_q2 : g_k2;
#pragma unroll
                for (int rp = 0; rp < 2; rp++) {
                    const int r = row + rp * 8;
                    const float vx = rp ? v10 : v00;
                    const float vy = rp ? v11 : v01;
                    const int b  = r >> 11;
                    const int t  = r & 2047;
                    const size_t base = ((size_t)(b * H_ + h) * T_ + t) * 128 + d;
                    const uint16_t hx = f2bf(vx), hy = f2bf(vy);
                    const uint16_t lx = f2bf(vx - bf2f(hx)), ly = f2bf(vy - bf2f(hy));
                    *(uint32_t*)(dst + base)      = (uint32_t)hx | ((uint32_t)hy << 16);
                    *(uint32_t*)(dst + base + 64) = (uint32_t)lx | ((uint32_t)ly << 16);
                }
            }
        }
    }
}

// Merged projection GEMMs: grid (16, 32, 3); z=0 qk (split epi), z=1 v, z=2 g
__global__ void __launch_bounds__(256)
gemm_proj(const float* __restrict__ b_qk, const float* __restrict__ b_v,
          const float* __restrict__ b_g)
{
    const int z = blockIdx.z;
    if (z == 0)      gemm_body(g_x2, g_wqk2, b_qk, nullptr, 1024, 2048, 1);
    else if (z == 1) gemm_body(g_x2, g_wv2,  b_v,  g_v,     1024, 2048, 0);
    else             gemm_body(g_x2, g_wg2,  b_g,  g_g,     1024, 2048, 0);
}

__global__ void __launch_bounds__(256)
gemm_out(const float* __restrict__ b_o, float* __restrict__ out)
{
    gemm_body(g_y2, g_wo2, b_o, out, 2048, 1024, 0);
}

// ---------------------------------------------------------------------------
// mma.sync retention attention ([hi|lo], 3-term virtual loop), fused
// RMSNorm + gating; writes g_y2 directly.  R11 structure (S via smem,
// vacc[8][4], Q from smem each tile), single-barrier tile loop:
//   wait<0>; __syncthreads; issueKV(kt+1); compute.
// smem: Q 16K | S 16K | K 2x16K | V 2x32K | reductions = 131840 B
// ---------------------------------------------------------------------------
#define AT_SQ   0
#define AT_SS   16384
#define AT_SK   32768
#define AT_SV   65536
#define AT_RA   131072
#define AT_RS   131328
#define AT_SMEM 131840

__global__ void __launch_bounds__(256)
retention_attn_mma()
{
    extern __shared__ __align__(128) char smx[];
    const uint32_t sb = smem_u32(smx);
    float* rowAbsS = (float*)(smx + AT_RA);
    float* rssS    = (float*)(smx + AT_RS);

    const int tid = threadIdx.x;
    const int wid = tid >> 5;
    const int lid = tid & 31;
    const int q   = lid >> 3;
    const int l7  = lid & 7;
    const int m_w = wid & 3;
    const int n_w = wid >> 2;
    const int gr  = lid >> 2;
    const int gc  = (lid & 3) * 2;

    const int qi = gridDim.x - 1 - blockIdx.x;   // big CTAs first
    const int h  = blockIdx.y;
    const int b  = blockIdx.z;
    const int t0 = qi * 64;
    const int bh = b * H_ + h;

    const float gamma = log1pf(-exp2f(-5.0f - (float)h));
    const float em1g  = expm1f(gamma);

    const int r0 = m_w * 16 + gr;
    const int r1 = r0 + 8;
    float rowfac[2];
#pragma unroll
    for (int hrow = 0; hrow < 2; hrow++) {
        const int rl = r0 + hrow * 8;
        const int t  = t0 + rl;
        const float sc2 = expm1f(gamma * (float)(t + 1)) / em1g;
        rowfac[hrow] = expf(gamma * (float)rl) * rsqrtf(sc2);
    }
    float ecl[4][2];
#pragma unroll
    for (int nt = 0; nt < 4; nt++)
#pragma unroll
        for (int cc = 0; cc < 2; cc++)
            ecl[nt][cc] = expf(-gamma * (float)(n_w * 32 + nt * 8 + gc + cc));

    if (tid < 64) rowAbsS[tid] = 0.f;

    auto issueKV = [&](int kt, int st) {
        const int s0 = kt * 64;
#pragma unroll
        for (int it = 0; it < 4; it++) {
            const int unit = tid + it * 256;
            const int seg = unit >> 9, rem = unit & 511;
            const int row = rem >> 3,  u   = rem & 7;
            cp_async16(sb + AT_SK + st * 16384 + seg * 8192 + row * 128 + ((u ^ (row & 7)) * 16),
                       g_k2 + ((size_t)bh * T_ + s0 + row) * 128 + seg * 64 + u * 8);
        }
#pragma unroll
        for (int it = 0; it < 8; it++) {
            const int unit = tid + it * 256;
            const int seg = unit >> 10, rem = unit & 1023;
            const int row = rem >> 3,   u   = rem & 7;
            cp_async16(sb + AT_SV + st * 32768 + seg * 16384 + row * 128 + ((u ^ (row & 7)) * 16),
                       g_vt2 + ((size_t)bh * 128 + row) * 4096 + seg * 2048 + s0 + u * 8);
        }
        cp_commit();
    };

    // prologue: Q (own group) + KV tile 0
    {
#pragma unroll
        for (int it = 0; it < 4; it++) {
            const int unit = tid + it * 256;
            const int seg = unit >> 9, rem = unit & 511;
            const int row = rem >> 3,  u   = rem & 7;
            cp_async16(sb + AT_SQ + seg * 8192 + row * 128 + ((u ^ (row & 7)) * 16),
                       g_q2 + ((size_t)bh * T_ + t0 + row) * 128 + seg * 64 + u * 8);
        }
        cp_commit();
        issueKV(0, 0);
    }

    float vacc[8][4];
#pragma unroll
    for (int i = 0; i < 8; i++)
#pragma unroll
        for (int r = 0; r < 4; r++) vacc[i][r] = 0.f;

    for (int kt = 0; kt <= qi; kt++) {
        const int s0 = kt * 64;
        const int st = kt & 1;
        cp_wait<0>();
        __syncthreads();
        if (kt < qi) issueKV(kt + 1, st ^ 1);

        // ---- QK^T ----
        float sacc[4][4];
#pragma unroll
        for (int i = 0; i < 4; i++)
#pragma unroll
            for (int r = 0; r < 4; r++) sacc[i][r] = 0.f;

#pragma unroll
        for (int c = 0; c < 3; c++) {
            const uint32_t aB = sb + AT_SQ + ((c == 2) ? 8192 : 0);
            const uint32_t bB = sb + AT_SK + st * 16384 + ((c == 1) ? 8192 : 0);
#pragma unroll
            for (int ks = 0; ks < 4; ks++) {
                uint32_t af[4];
                {
                    const int row = m_w * 16 + (q & 1) * 8 + l7;
                    const int su  = (ks * 2 + (q >> 1)) ^ (row & 7);
                    ldmatrix_x4(af, aB + row * 128 + su * 16);
                }
                uint32_t bf[2][4];
#pragma unroll
                for (int np = 0; np < 2; np++) {
                    const int row = n_w * 32 + np * 16 + (q >> 1) * 8 + l7;
                    const int su  = (ks * 2 + (q & 1)) ^ (row & 7);
                    ldmatrix_x4(bf[np], bB + row * 128 + su * 16);
                }
#pragma unroll
                for (int nt = 0; nt < 4; nt++)
                    mma16816(sacc[nt], af,
                             bf[nt >> 1][(nt & 1) * 2], bf[nt >> 1][(nt & 1) * 2 + 1]);
            }
        }

        // ---- mask/decay, rowAbs, convert -> S [hi|lo] (warp-local rows) ----
        const float e_ts = expf(gamma * (float)(t0 - s0));
        const bool diag = (s0 == t0);
        float pa[2] = {0.f, 0.f};
#pragma unroll
        for (int nt = 0; nt < 4; nt++) {
#pragma unroll
            for (int hrow = 0; hrow < 2; hrow++) {
                const int rl = r0 + hrow * 8;
                uint16_t hi[2], lo[2];
#pragma unroll
                for (int cc = 0; cc < 2; cc++) {
                    const int cl = n_w * 32 + nt * 8 + gc + cc;
                    float v = sacc[nt][hrow * 2 + cc] * rowfac[hrow] * (e_ts * ecl[nt][cc]);
                    if (diag && cl > rl) v = 0.f;
                    pa[hrow] += fabsf(v);
                    hi[cc] = f2bf(v);
                    lo[cc] = f2bf(v - bf2f(hi[cc]));
                }
                const int cl0 = n_w * 32 + nt * 8 + gc;
                const uint32_t hp = (uint32_t)hi[0] | ((uint32_t)hi[1] << 16);
                const uint32_t lp = (uint32_t)lo[0] | ((uint32_t)lo[1] << 16);
                const uint32_t byo = rl * 128 + (((cl0 >> 3) ^ (rl & 7)) * 16) + (cl0 & 7) * 2;
                *(uint32_t*)(smx + AT_SS + byo)        = hp;
                *(uint32_t*)(smx + AT_SS + 8192 + byo) = lp;
            }
        }
        pa[0] += __shfl_xor_sync(0xffffffffu, pa[0], 1);
        pa[0] += __shfl_xor_sync(0xffffffffu, pa[0], 2);
        pa[1] += __shfl_xor_sync(0xffffffffu, pa[1], 1);
        pa[1] += __shfl_xor_sync(0xffffffffu, pa[1], 2);
        if ((lid & 3) == 0) {
            atomicAdd(&rowAbsS[r0], pa[0]);
            atomicAdd(&rowAbsS[r1], pa[1]);
        }
        // S rows are produced and consumed by the SAME warp.
        __syncwarp();

        // ---- S @ V ----
#pragma unroll
        for (int c = 0; c < 3; c++) {
            const uint32_t aB = sb + AT_SS + ((c == 2) ? 8192 : 0);
            const uint32_t bB = sb + AT_SV + st * 32768 + ((c == 1) ? 16384 : 0);
#pragma unroll
            for (int ks = 0; ks < 4; ks++) {
                uint32_t af[4];
                {
                    const int row = m_w * 16 + (q & 1) * 8 + l7;
                    const int su  = (ks * 2 + (q >> 1)) ^ (row & 7);
                    ldmatrix_x4(af, aB + row * 128 + su * 16);
                }
                uint32_t bf[4][4];
#pragma unroll
                for (int np = 0; np < 4; np++) {
                    const int row = n_w * 64 + np * 16 + (q >> 1) * 8 + l7;
                    const int su  = (ks * 2 + (q & 1)) ^ (row & 7);
                    ldmatrix_x4(bf[np], bB + row * 128 + su * 16);
                }
#pragma unroll
                for (int nt = 0; nt < 8; nt++)
                    mma16816(vacc[nt], af,
                             bf[nt >> 1][(nt & 1) * 2], bf[nt >> 1][(nt & 1) * 2 + 1]);
            }
        }
        // no trailing sync: the next iteration's top sync protects stage reuse
    }
    __syncthreads();   // make final-tile rowAbs atomics visible to epilogue

    // ---- epilogue ----
    const float den0 = fminf(fmaxf(rowAbsS[r0], 1.0f), 50000.0f);
    const float den1 = fminf(fmaxf(rowAbsS[r1], 1.0f), 50000.0f);
    const float inv[2] = {1.0f / den0, 1.0f / den1};

    float ss[2] = {0.f, 0.f};
#pragma unroll
    for (int nt = 0; nt < 8; nt++)
#pragma unroll
        for (int hrow = 0; hrow < 2; hrow++)
#pragma unroll
            for (int cc = 0; cc < 2; cc++) {
                const float o = vacc[nt][hrow * 2 + cc] * inv[hrow];
                ss[hrow] = fmaf(o, o, ss[hrow]);
            }
    ss[0] += __shfl_xor_sync(0xffffffffu, ss[0], 1);
    ss[0] += __shfl_xor_sync(0xffffffffu, ss[0], 2);
    ss[1] += __shfl_xor_sync(0xffffffffu, ss[1], 1);
    ss[1] += __shfl_xor_sync(0xffffffffu, ss[1], 2);
    if ((lid & 3) == 0) {
        rssS[r0 * 2 + n_w] = ss[0];
        rssS[r1 * 2 + n_w] = ss[1];
    }
    __syncthreads();

    float rstd[2];
#pragma unroll
    for (int hrow = 0; hrow < 2; hrow++) {
        const int rl = r0 + hrow * 8;
        rstd[hrow] = rsqrtf((rssS[rl * 2] + rssS[rl * 2 + 1]) * (1.0f / 128.0f)
                            + 1.1920929e-7f);
    }

#pragma unroll
    for (int hrow = 0; hrow < 2; hrow++) {
        const int rl = r0 + hrow * 8;
        const int t  = t0 + rl;
        const size_t gbase = ((size_t)(b * T_ + t)) * VBD_ + (size_t)h * VD_;
        const size_t ybase = ((size_t)(b * T_ + t)) * 4096 + (size_t)h * VD_;
#pragma unroll
        for (int nt = 0; nt < 8; nt++) {
            const int v = n_w * 64 + nt * 8 + gc;
            const float2 gv = *(const float2*)(g_g + gbase + v);
            float ox = vacc[nt][hrow * 2 + 0] * inv[hrow] * rstd[hrow] * gv.x;
            float oy = vacc[nt][hrow * 2 + 1] * inv[hrow] * rstd[hrow] * gv.y;
            uint16_t hx = f2bf(ox), hy = f2bf(oy);
            uint16_t lx = f2bf(ox - bf2f(hx)), ly = f2bf(oy - bf2f(hy));
            *(uint32_t*)(g_y2 + ybase + v)        = (uint32_t)hx | ((uint32_t)hy << 16);
            *(uint32_t*)(g_y2 + ybase + 2048 + v) = (uint32_t)lx | ((uint32_t)ly << 16);
        }
    }
}

// ---------------------------------------------------------------------------
// Launch
// ---------------------------------------------------------------------------
extern "C" void kernel_launch(void* const* d_in, const int* in_sizes, int n_in,
                              void* d_out, int out_size)
{
    const float* x    = (const float*)d_in[0];
    const float* W_qk = (const float*)d_in[1];
    const float* b_qk = (const float*)d_in[2];
    const float* W_v  = (const float*)d_in[3];
    const float* b_v  = (const float*)d_in[4];
    const float* W_g  = (const float*)d_in[5];
    const float* b_g  = (const float*)d_in[6];
    const float* W_o  = (const float*)d_in[7];
    const float* b_o  = (const float*)d_in[8];
    float* out = (float*)d_out;

    uint16_t *x2;
    cudaGetSymbolAddress((void**)&x2, g_x2);
    cudaFuncSetAttribute(gemm_proj,
                         cudaFuncAttributeMaxDynamicSharedMemorySize, GEMM_SMEM_BYTES);
    cudaFuncSetAttribute(gemm_out,
                         cudaFuncAttributeMaxDynamicSharedMemorySize, GEMM_SMEM_BYTES);
    cudaFuncSetAttribute(retention_attn_mma,
                         cudaFuncAttributeMaxDynamicSharedMemorySize, AT_SMEM);

    // --- split/transpose GEMM operands ([hi|lo]) ---
    {
        split_rows<<<(M_ * (C_ / 4) + 255) / 256, 256>>>(x, x2, M_, C_);
        dim3 bt(32, 8);
        split_transpose_all<<<dim3(64, 64, 4), bt>>>(W_qk, W_v, W_g, W_o);
    }

    // --- merged projection GEMMs: CTA 128x128 (z: qk | v | g) ---
    {
        dim3 g(2048 / 128, M_ / 128, 3);
        gemm_proj<<<g, 256, GEMM_SMEM_BYTES>>>(b_qk, b_v, b_g);
    }

    // --- V transpose/split ---
    {
        dim3 bt(32, 8);
        transpose_split_v<<<dim3(T_ / 32, VD_ / 32, B_ * H_), bt>>>();
    }

    // --- attention (R11 pipeline, single-barrier loop; writes g_y2) ---
    {
        dim3 gAttn(T_ / 64, H_, B_);
        retention_attn_mma<<<gAttn, 256, AT_SMEM>>>();
    }

    // --- output GEMM: CTA 128x128 ---
    {
        dim3 g(1024 / 128, M_ / 128);
        gemm_out<<<g, 256, GEMM_SMEM_BYTES>>>(b_o, out);
    }

    (void)in_sizes; (void)n_in; (void)out_size;
}